// round 1
// baseline (speedup 1.0000x reference)
#include <cuda_runtime.h>
#include <cuda_bf16.h>

#define A_N      4096
#define N_OBJ    8192
#define IN_DIM   16
#define EMBED    128
#define MAX_OBJ  16
#define DEG      8
#define OBS_DEG  8
#define POS_DIM  2
#define ORIG     18          // IN_DIM + POS_DIM
#define OUTC     288         // MAX_OBJ * ORIG
#define NLOG     17          // MAX_OBJ + 1
#define KTOT     128         // DEG * MAX_OBJ
#define THRES    0.02f

// scratch: per-agent encoding (stage 1 -> stage 2 handoff)
__device__ float g_enc[A_N * EMBED];

// ---------------------------------------------------------------------------
// Kernel A: obs encode.  One block per agent, 128 threads (one per channel).
//   msg[e] = concat(obj_x[o], obj_pos[o]-agent_pos[a])   (18)
//   h = relu(msg @ W1 + b1); S = sum_e h; enc = S @ W2 + b2
// ---------------------------------------------------------------------------
__global__ __launch_bounds__(128) void enc_kernel(
    const float* __restrict__ obj_x, const float* __restrict__ obj_pos,
    const float* __restrict__ agent_pos,
    const float* __restrict__ W1, const float* __restrict__ b1,
    const float* __restrict__ W2, const float* __restrict__ b2,
    const int*   __restrict__ obs_src)
{
    const int a = blockIdx.x;
    const int t = threadIdx.x;

    __shared__ float msg[OBS_DEG][ORIG];
    __shared__ float S[EMBED];
    __shared__ float apos[2];

    if (t < 2) apos[t] = agent_pos[2 * a + t];
    __syncthreads();

    // cooperatively build the 8 messages (8*18 = 144 entries)
    for (int idx = t; idx < OBS_DEG * ORIG; idx += 128) {
        const int e = idx / ORIG;
        const int k = idx - e * ORIG;
        const int o = obs_src[a * OBS_DEG + e];
        float v;
        if (k < IN_DIM) v = obj_x[o * IN_DIM + k];
        else            v = obj_pos[o * POS_DIM + (k - IN_DIM)] - apos[k - IN_DIM];
        msg[e][k] = v;
    }
    __syncthreads();

    // hoist W1 column t into registers
    float w[ORIG];
#pragma unroll
    for (int k = 0; k < ORIG; k++) w[k] = W1[k * EMBED + t];
    const float b1t = b1[t];

    float acc = 0.f;
#pragma unroll
    for (int e = 0; e < OBS_DEG; e++) {
        float h = b1t;
        const float2* row = (const float2*)msg[e];
#pragma unroll
        for (int q = 0; q < 9; q++) {
            float2 p = row[q];
            h = fmaf(p.x, w[2 * q], h);
            h = fmaf(p.y, w[2 * q + 1], h);
        }
        acc += fmaxf(h, 0.f);
    }
    S[t] = acc;
    __syncthreads();

    float out = b2[t];
    const float4* S4 = (const float4*)S;
#pragma unroll 4
    for (int k4 = 0; k4 < EMBED / 4; k4++) {
        float4 s = S4[k4];
        const int k = 4 * k4;
        out = fmaf(s.x, W2[(k    ) * EMBED + t], out);
        out = fmaf(s.y, W2[(k + 1) * EMBED + t], out);
        out = fmaf(s.z, W2[(k + 2) * EMBED + t], out);
        out = fmaf(s.w, W2[(k + 3) * EMBED + t], out);
    }
    g_enc[a * EMBED + t] = out;
}

// ---------------------------------------------------------------------------
// Kernel B: per-agent comm decode + dedup + merge + final decode.
// One block per agent i, 128 threads.  All 8 incoming edges processed
// together so each mdec_Wx load feeds 8 FMAs (register tiling over edges).
// ---------------------------------------------------------------------------
__global__ __launch_bounds__(128) void agent_kernel(
    const float* __restrict__ agent_pos,
    const float* __restrict__ mdec_Ws, const float* __restrict__ mdec_bs,
    const float* __restrict__ mdec_Wx, const float* __restrict__ mdec_bx,
    const float* __restrict__ menc_W1, const float* __restrict__ menc_b1,
    const float* __restrict__ menc_W2, const float* __restrict__ menc_b2,
    const float* __restrict__ dec_Ws,  const float* __restrict__ dec_bs,
    const float* __restrict__ dec_Wx,  const float* __restrict__ dec_bx,
    const int*   __restrict__ comm_src,
    float* __restrict__ out, int write_extra)
{
    const int i = blockIdx.x;
    const int t = threadIdx.x;

    __shared__ float zj[DEG][EMBED];        // 4 KB
    __shared__ float cand[KTOT][ORIG];      // 9 KB
    __shared__ float logits[DEG][NLOG];
    __shared__ int   npred[DEG];
    __shared__ int   keepf[KTOT];
    __shared__ float px[KTOT], py[KTOT];
    __shared__ float relx[DEG], rely[DEG];
    __shared__ int   jidx[DEG];
    __shared__ float Spre[EMBED];
    __shared__ float mergeds[EMBED];
    __shared__ float dlog[NLOG];
    __shared__ int   n2s;

    if (t < DEG) {
        const int j = comm_src[i * DEG + t];
        jidx[t] = j;
        relx[t] = agent_pos[2 * j    ] - agent_pos[2 * i    ];
        rely[t] = agent_pos[2 * j + 1] - agent_pos[2 * i + 1];
    }
    __syncthreads();
#pragma unroll
    for (int e = 0; e < DEG; e++) zj[e][t] = g_enc[jidx[e] * EMBED + t];
    __syncthreads();

    // ---- mdec elems: 288 outputs, thread t handles cols {t, t+128, t+256} ----
#pragma unroll
    for (int ci = 0; ci < 3; ci++) {
        const int c = t + ci * 128;
        if (c < OUTC) {
            float acc[DEG];
            const float bx = mdec_bx[c];
#pragma unroll
            for (int e = 0; e < DEG; e++) acc[e] = bx;
            for (int k = 0; k < EMBED; k += 4) {
                const float w0 = mdec_Wx[(k    ) * OUTC + c];
                const float w1 = mdec_Wx[(k + 1) * OUTC + c];
                const float w2 = mdec_Wx[(k + 2) * OUTC + c];
                const float w3 = mdec_Wx[(k + 3) * OUTC + c];
#pragma unroll
                for (int e = 0; e < DEG; e++) {
                    float4 z = *(const float4*)&zj[e][k];
                    acc[e] = fmaf(z.x, w0, acc[e]);
                    acc[e] = fmaf(z.y, w1, acc[e]);
                    acc[e] = fmaf(z.z, w2, acc[e]);
                    acc[e] = fmaf(z.w, w3, acc[e]);
                }
            }
            const int m = c / ORIG;
            const int dim = c - m * ORIG;
#pragma unroll
            for (int e = 0; e < DEG; e++) {
                float v = acc[e];
                if (dim == 16) v += relx[e];
                if (dim == 17) v += rely[e];
                cand[e * MAX_OBJ + m][dim] = v;
            }
        }
    }
    // ---- mdec logits (threads 0..16) ----
    if (t < NLOG) {
        float acc[DEG];
        const float bs = mdec_bs[t];
#pragma unroll
        for (int e = 0; e < DEG; e++) acc[e] = bs;
        for (int k = 0; k < EMBED; k += 4) {
            const float w0 = mdec_Ws[(k    ) * NLOG + t];
            const float w1 = mdec_Ws[(k + 1) * NLOG + t];
            const float w2 = mdec_Ws[(k + 2) * NLOG + t];
            const float w3 = mdec_Ws[(k + 3) * NLOG + t];
#pragma unroll
            for (int e = 0; e < DEG; e++) {
                float4 z = *(const float4*)&zj[e][k];
                acc[e] = fmaf(z.x, w0, acc[e]);
                acc[e] = fmaf(z.y, w1, acc[e]);
                acc[e] = fmaf(z.z, w2, acc[e]);
                acc[e] = fmaf(z.w, w3, acc[e]);
            }
        }
#pragma unroll
        for (int e = 0; e < DEG; e++) logits[e][t] = acc[e];
    }
    __syncthreads();

    // argmax per edge (first max, matching jnp.argmax)
    if (t < DEG) {
        float best = logits[t][0]; int bi = 0;
#pragma unroll
        for (int c = 1; c < NLOG; c++) {
            const float v = logits[t][c];
            if (v > best) { best = v; bi = c; }
        }
        npred[t] = bi;
    }
    __syncthreads();

    // validity + extract positions
    {
        const int e = t >> 4, m = t & 15;
        keepf[t] = (m < npred[e]) ? 1 : 0;
        px[t] = cand[t][16];
        py[t] = cand[t][17];
    }
    __syncthreads();

    // dedup: element l dies if any valid k<l is within THRES
    {
        const int v = keepf[t];
        int dead = 0;
        const float x = px[t], y = py[t];
        if (v) {
            for (int k = 0; k < t; k++) {
                if (keepf[k]) {
                    const float dx = x - px[k];
                    const float dy = y - py[k];
                    if (sqrtf(dx * dx + dy * dy) < THRES) dead = 1;
                }
            }
        }
        __syncthreads();             // all reads of original validity done
        keepf[t] = (v && !dead) ? 1 : 0;
    }
    __syncthreads();

    // cumsum cap: at most MAX_OBJ-1 kept
    if (t == 0) {
        int cnt = 0;
        for (int l = 0; l < KTOT; l++) {
            if (keepf[l]) { cnt++; if (cnt > MAX_OBJ - 1) keepf[l] = 0; }
        }
    }
    __syncthreads();

    // ---- merge encode: Spre[c] = sum over kept l of relu(cand[l] . W1[:,c] + b1[c]) ----
    {
        float w1r[ORIG];
#pragma unroll
        for (int k = 0; k < ORIG; k++) w1r[k] = menc_W1[k * EMBED + t];
        const float b1t = menc_b1[t];
        float acc = 0.f;
        for (int l = 0; l < KTOT; l++) {
            if (keepf[l]) {
                const float2* row = (const float2*)cand[l];
                float h = b1t;
#pragma unroll
                for (int q = 0; q < 9; q++) {
                    float2 p = row[q];
                    h = fmaf(p.x, w1r[2 * q], h);
                    h = fmaf(p.y, w1r[2 * q + 1], h);
                }
                acc += fmaxf(h, 0.f);
            }
        }
        Spre[t] = acc;
    }
    __syncthreads();

    // merged = Spre @ menc_W2 + b2
    {
        float mg = menc_b2[t];
        const float4* S4 = (const float4*)Spre;
#pragma unroll 4
        for (int k4 = 0; k4 < EMBED / 4; k4++) {
            float4 s = S4[k4];
            const int k = 4 * k4;
            mg = fmaf(s.x, menc_W2[(k    ) * EMBED + t], mg);
            mg = fmaf(s.y, menc_W2[(k + 1) * EMBED + t], mg);
            mg = fmaf(s.z, menc_W2[(k + 2) * EMBED + t], mg);
            mg = fmaf(s.w, menc_W2[(k + 3) * EMBED + t], mg);
        }
        mergeds[t] = mg;
    }
    __syncthreads();

    // dec logits -> n2
    if (t < NLOG) {
        float a2 = dec_bs[t];
        const float4* M4 = (const float4*)mergeds;
        for (int k4 = 0; k4 < EMBED / 4; k4++) {
            float4 s = M4[k4];
            const int k = 4 * k4;
            a2 = fmaf(s.x, dec_Ws[(k    ) * NLOG + t], a2);
            a2 = fmaf(s.y, dec_Ws[(k + 1) * NLOG + t], a2);
            a2 = fmaf(s.z, dec_Ws[(k + 2) * NLOG + t], a2);
            a2 = fmaf(s.w, dec_Ws[(k + 3) * NLOG + t], a2);
        }
        dlog[t] = a2;
    }
    __syncthreads();
    if (t == 0) {
        float best = dlog[0]; int bi = 0;
#pragma unroll
        for (int c = 1; c < NLOG; c++) {
            if (dlog[c] > best) { best = dlog[c]; bi = c; }
        }
        n2s = bi;
    }
    __syncthreads();
    const int n2 = n2s;

    // decoded = (merged @ dec_Wx + dec_bx).reshape(16,18) * mask
#pragma unroll
    for (int ci = 0; ci < 3; ci++) {
        const int c = t + ci * 128;
        if (c < OUTC) {
            float v = dec_bx[c];
            const float4* M4 = (const float4*)mergeds;
            for (int k4 = 0; k4 < EMBED / 4; k4++) {
                float4 s = M4[k4];
                const int k = 4 * k4;
                v = fmaf(s.x, dec_Wx[(k    ) * OUTC + c], v);
                v = fmaf(s.y, dec_Wx[(k + 1) * OUTC + c], v);
                v = fmaf(s.z, dec_Wx[(k + 2) * OUTC + c], v);
                v = fmaf(s.w, dec_Wx[(k + 3) * OUTC + c], v);
            }
            const int m = c / ORIG;
            out[(size_t)i * OUTC + c] = (m < n2) ? v : 0.f;
        }
    }

    // batch + mask tails (written as output dtype float32)
    if (write_extra && t < MAX_OBJ) {
        const size_t batch_off = (size_t)A_N * OUTC;
        const size_t mask_off  = batch_off + (size_t)A_N * MAX_OBJ;
        out[batch_off + (size_t)i * MAX_OBJ + t] = (float)i;
        out[mask_off  + (size_t)i * MAX_OBJ + t] = (t < n2) ? 1.f : 0.f;
    }
}

extern "C" void kernel_launch(void* const* d_in, const int* in_sizes, int n_in,
                              void* d_out, int out_size) {
    const float* obj_x     = (const float*)d_in[0];
    const float* obj_pos   = (const float*)d_in[1];
    const float* agent_pos = (const float*)d_in[2];
    const float* enc_W1    = (const float*)d_in[3];
    const float* enc_b1    = (const float*)d_in[4];
    const float* enc_W2    = (const float*)d_in[5];
    const float* enc_b2    = (const float*)d_in[6];
    const float* mdec_Ws   = (const float*)d_in[7];
    const float* mdec_bs   = (const float*)d_in[8];
    const float* mdec_Wx   = (const float*)d_in[9];
    const float* mdec_bx   = (const float*)d_in[10];
    const float* menc_W1   = (const float*)d_in[11];
    const float* menc_b1   = (const float*)d_in[12];
    const float* menc_W2   = (const float*)d_in[13];
    const float* menc_b2   = (const float*)d_in[14];
    const float* dec_Ws    = (const float*)d_in[15];
    const float* dec_bs    = (const float*)d_in[16];
    const float* dec_Wx    = (const float*)d_in[17];
    const float* dec_bx    = (const float*)d_in[18];
    const int*   obs_ei    = (const int*)d_in[19];   // row0 = tgt, row1 = src
    const int*   comm_ei   = (const int*)d_in[20];   // row0 = src(j), row1 = tgt(i)

    const int* obs_src  = obs_ei  + A_N * OBS_DEG;   // row 1
    const int* comm_src = comm_ei;                   // row 0

    enc_kernel<<<A_N, 128>>>(obj_x, obj_pos, agent_pos,
                             enc_W1, enc_b1, enc_W2, enc_b2, obs_src);

    const int full = A_N * OUTC + 2 * A_N * MAX_OBJ;   // decoded + batch + mask
    const int write_extra = (out_size >= full) ? 1 : 0;

    agent_kernel<<<A_N, 128>>>(agent_pos,
                               mdec_Ws, mdec_bs, mdec_Wx, mdec_bx,
                               menc_W1, menc_b1, menc_W2, menc_b2,
                               dec_Ws, dec_bs, dec_Wx, dec_bx,
                               comm_src, (float*)d_out, write_extra);
}